// round 14
// baseline (speedup 1.0000x reference)
#include <cuda_runtime.h>
#include <cuda_bf16.h>
#include <math.h>

#define D 128
#define NMAX 100000
#define EMAX 620000
#define SCAN_B 512

// Static scratch (no allocations allowed)
__device__ __nv_bfloat16 g_aggbf[(size_t)NMAX * D];   // 25.6 MB, both layers
__device__ float g_h[(size_t)NMAX * D];
__device__ int   g_cnt [NMAX];
__device__ int   g_ptr [NMAX];     // exclusive prefix; post-fill: ptr[i]=excl[i+1]
__device__ int   g_bsum[256];
__device__ int   g_boff[256];
__device__ unsigned g_ebuf[EMAX];  // src | (type<<17)

__device__ __forceinline__ void red_add_v4(float* p, float4 v) {
    asm volatile("red.global.add.v4.f32 [%0], {%1,%2,%3,%4};"
                 :: "l"(p), "f"(v.x), "f"(v.y), "f"(v.z), "f"(v.w) : "memory");
}

__device__ __forceinline__ float tanh_approx(float x) {
    float y;
    asm("tanh.approx.f32 %0, %1;" : "=f"(y) : "f"(x));
    return y;
}

__device__ __forceinline__ void cp16(unsigned saddr, const void* g, int srcsize) {
    asm volatile("cp.async.cg.shared.global [%0], [%1], 16, %2;"
                 :: "r"(saddr), "l"(g), "r"(srcsize));
}

// ---------------------------------------------------------------------------
// CSR build
// ---------------------------------------------------------------------------
__global__ void deg_count(const int* __restrict__ ei, int E) {
    int i = blockIdx.x * blockDim.x + threadIdx.x;
    if (i < E) atomicAdd(&g_cnt[__ldg(ei + E + i)], 1);
}

__global__ void scan1(int Nn) {
    __shared__ int warpsums[16];
    int i = blockIdx.x * SCAN_B + threadIdx.x;
    int lane = threadIdx.x & 31, w = threadIdx.x >> 5;
    int v = (i < Nn) ? g_cnt[i] : 0;
    int s = v;
    #pragma unroll
    for (int o = 1; o < 32; o <<= 1) {
        int t = __shfl_up_sync(~0u, s, o);
        if (lane >= o) s += t;
    }
    if (lane == 31) warpsums[w] = s;
    __syncthreads();
    if (w == 0) {
        int ws = (lane < 16) ? warpsums[lane] : 0;
        #pragma unroll
        for (int o = 1; o < 16; o <<= 1) {
            int t = __shfl_up_sync(~0u, ws, o);
            if (lane >= o) ws += t;
        }
        if (lane < 16) warpsums[lane] = ws;
    }
    __syncthreads();
    int base = (w > 0) ? warpsums[w - 1] : 0;
    if (i < Nn) g_ptr[i] = base + s - v;
    if (threadIdx.x == SCAN_B - 1) g_bsum[blockIdx.x] = base + s;
}

// Parallel block-scan over per-block sums (nb <= 256); one 256-thread block.
__global__ void scan2(int nb) {
    __shared__ int warpsums[8];
    int i = threadIdx.x;
    int lane = i & 31, w = i >> 5;
    int v = (i < nb) ? g_bsum[i] : 0;
    int s = v;
    #pragma unroll
    for (int o = 1; o < 32; o <<= 1) {
        int t = __shfl_up_sync(~0u, s, o);
        if (lane >= o) s += t;
    }
    if (lane == 31) warpsums[w] = s;
    __syncthreads();
    if (w == 0) {
        int ws = (lane < 8) ? warpsums[lane] : 0;
        #pragma unroll
        for (int o = 1; o < 8; o <<= 1) {
            int t = __shfl_up_sync(~0u, ws, o);
            if (lane >= o) ws += t;
        }
        if (lane < 8) warpsums[lane] = ws;
    }
    __syncthreads();
    int base = (w > 0) ? warpsums[w - 1] : 0;
    if (i < nb) g_boff[i] = base + s - v;   // exclusive prefix
}

__global__ void scan3(int Nn) {
    int i = blockIdx.x * blockDim.x + threadIdx.x;
    if (i < Nn) g_ptr[i] += g_boff[i / SCAN_B];
}

// Bumps g_ptr[dst] itself: afterwards ptr[i] == exclusive_prefix[i+1].
__global__ void csr_fill(const int* __restrict__ ei, const int* __restrict__ et, int E) {
    int e = blockIdx.x * blockDim.x + threadIdx.x;
    if (e < E) {
        int dst = __ldg(ei + E + e);
        int p = atomicAdd(&g_ptr[dst], 1);
        g_ebuf[p] = (unsigned)__ldg(ei + e) | ((unsigned)__ldg(et + e) << 17);
    }
}

// ---------------------------------------------------------------------------
// Gather conv: warp per destination; writes NORMALIZED agg in bf16.
// After csr_fill: beg = ptr[node-1] (0 for node 0), end = ptr[node].
// ---------------------------------------------------------------------------
__global__ __launch_bounds__(256)
void conv_gather(const float* __restrict__ x,
                 const float* __restrict__ rel,
                 __nv_bfloat16* __restrict__ agg,
                 int Nn)
{
    int node = blockIdx.x * (blockDim.x >> 5) + (threadIdx.x >> 5);
    if (node >= Nn) return;
    int lane = threadIdx.x & 31;
    int beg = (node == 0) ? 0 : __ldg(&g_ptr[node - 1]);
    int end = __ldg(&g_ptr[node]);
    float4 acc = make_float4(0.f, 0.f, 0.f, 0.f);
    for (int i = beg; i < end; i++) {
        unsigned e = __ldg(&g_ebuf[i]);
        int src = e & 0x1FFFF;
        int typ = e >> 17;
        float4 xv = reinterpret_cast<const float4*>(x   + (size_t)src * D)[lane];
        float4 rv = reinterpret_cast<const float4*>(rel + (size_t)typ * D)[lane];
        acc.x += xv.x * rv.x; acc.y += xv.y * rv.y;
        acc.z += xv.z * rv.z; acc.w += xv.w * rv.w;
    }
    float inv = 1.0f / fmaxf((float)(end - beg), 1.0f);
    __nv_bfloat162 p01 = __floats2bfloat162_rn(acc.x * inv, acc.y * inv);
    __nv_bfloat162 p23 = __floats2bfloat162_rn(acc.z * inv, acc.w * inv);
    unsigned u0 = *reinterpret_cast<unsigned*>(&p01);
    unsigned u1 = *reinterpret_cast<unsigned*>(&p23);
    reinterpret_cast<uint2*>(agg + (size_t)node * D)[lane] = make_uint2(u0, u1);
}

// ---------------------------------------------------------------------------
// Fused jump scatter + change passthrough (disjoint outputs, one kernel):
//   blocks [0, copyBlocks):        out_change = change      (pure bandwidth)
//   blocks [copyBlocks, gridDim):  out_dch[dst] += jw*ew[e]*emb[src] (atomics)
// The streaming copy fills DRAM headroom under the scatter's latency.
// ---------------------------------------------------------------------------
__global__ __launch_bounds__(256)
void jump_and_copy(const float* __restrict__ emb,
                   const float* __restrict__ ew,
                   const float* __restrict__ jwp,
                   const int* __restrict__ ej,
                   float* __restrict__ out_dch,
                   const float* __restrict__ change,
                   float* __restrict__ out_change,
                   int EJ, int Nn, int copyBlocks)
{
    if (blockIdx.x < copyBlocks) {
        size_t total4 = (size_t)Nn * D / 4;
        size_t stride = (size_t)copyBlocks * blockDim.x;
        for (size_t i = (size_t)blockIdx.x * blockDim.x + threadIdx.x;
             i < total4; i += stride) {
            reinterpret_cast<float4*>(out_change)[i] =
                reinterpret_cast<const float4*>(change)[i];
        }
        return;
    }
    float jw = __ldg(jwp);
    int lane = threadIdx.x & 31;
    int warp = (blockIdx.x - copyBlocks) * (blockDim.x >> 5) + (threadIdx.x >> 5);
    int nwarps = (gridDim.x - copyBlocks) * (blockDim.x >> 5);
    for (int e = warp; e < EJ; e += nwarps) {
        int src = __ldg(ej + e);
        int dst = __ldg(ej + EJ + e);
        float w = jw * __ldg(ew + e);
        float4 v = reinterpret_cast<const float4*>(emb + (size_t)src * D)[lane];
        v.x *= w; v.y *= w; v.z *= w; v.w *= w;
        red_add_v4(out_dch + (size_t)dst * D + lane * 4, v);
    }
}

// ---------------------------------------------------------------------------
// Pipelined fused GEMM (TRIPLE-buffered, prefetch distance 2):
//   out = x + res * tanh( aggbf @ Wa + x @ Wx )
// A split: agg half staged bf16 via cp.async (ldmatrix fragments),
//          x half staged fp32 (LDS+cvt fragments; epilogue reads it fp32).
// 512 threads = 16 warps (4 m x 4 n), 1 CTA/SM, smem ~218KB.
// ---------------------------------------------------------------------------
#define BM 64
#define ASB 136                               // bf16 per agg row (272B, padded)
#define ASX 132                               // fp32 per x row (528B, padded)
#define BS  136
#define NBUF 3
#define ABF_BYTES (BM * ASB * 2)              // 17408 per buf
#define AXF_BYTES (BM * ASX * 4)              // 33792 per buf
#define SMEM_B_OFF (NBUF * (ABF_BYTES + AXF_BYTES))   // 153600
#define SMEM_BYTES (SMEM_B_OFF + 256 * BS * 2)        // 223232

__global__ __launch_bounds__(512, 1)
void fused_gemm(const float* __restrict__ x,
                const float* __restrict__ Wa,
                const float* __restrict__ Wx,
                const float* __restrict__ resp,
                const __nv_bfloat16* __restrict__ aggbf,
                float* __restrict__ out,
                int Nn, int ntiles)
{
    extern __shared__ char smraw[];
    __nv_bfloat16* Abf = reinterpret_cast<__nv_bfloat16*>(smraw);             // [3][BM*ASB]
    float* Axf = reinterpret_cast<float*>(smraw + NBUF * ABF_BYTES);          // [3][BM*ASX]
    __nv_bfloat16* Bs = reinterpret_cast<__nv_bfloat16*>(smraw + SMEM_B_OFF);

    int tid  = threadIdx.x;
    int lane = tid & 31;
    int wid  = tid >> 5;
    int wm   = wid & 3;
    int wn   = wid >> 2;
    int g    = lane >> 2;
    int tg2  = (lane & 3) * 2;

    unsigned sAbf = (unsigned)__cvta_generic_to_shared(Abf);
    unsigned sAxf = (unsigned)__cvta_generic_to_shared(Axf);

    // ---- stage weights once (bf16) ----
    for (int idx = tid; idx < 256 * D / 4; idx += 512) {
        int k  = idx >> 5;
        int c4 = (idx & 31) * 4;
        const float* src = (k < D) ? (Wa + (size_t)k * D) : (Wx + (size_t)(k - D) * D);
        float4 v = *reinterpret_cast<const float4*>(src + c4);
        *reinterpret_cast<__nv_bfloat162*>(&Bs[k * BS + c4])     = __floats2bfloat162_rn(v.x, v.y);
        *reinterpret_cast<__nv_bfloat162*>(&Bs[k * BS + c4 + 2]) = __floats2bfloat162_rn(v.z, v.w);
    }

    float resv = __ldg(resp);
    int stride = gridDim.x;

    // staging: 48 16B-chunks per row (16 agg-bf16 + 32 x-fp32), 64 rows
    auto stage = [&](int tile, int buf) {
        int row0 = tile * BM;
        unsigned b_bf = sAbf + (unsigned)buf * ABF_BYTES;
        unsigned b_xf = sAxf + (unsigned)buf * AXF_BYTES;
        for (int i = tid; i < BM * 48; i += 512) {
            int r = i / 48, c = i % 48;
            int row = row0 + r;
            int ok = (row < Nn) ? 16 : 0;
            if (c < 16) {
                cp16(b_bf + (unsigned)(r * ASB + c * 8) * 2,
                     aggbf + (size_t)row * D + c * 8, ok);
            } else {
                int cx = c - 16;
                cp16(b_xf + (unsigned)(r * ASX + cx * 4) * 4,
                     x + (size_t)row * D + cx * 4, ok);
            }
        }
        asm volatile("cp.async.commit_group;" ::: "memory");
    };

    int t0 = blockIdx.x;
    stage(t0, 0);
    if (t0 + stride < ntiles) stage(t0 + stride, 1);

    int buf = 0;
    for (int t = t0; t < ntiles; t += stride) {
        int row0 = t * BM;
        // prefetch distance 2, then wait with EXACT pending count for buf
        int t2 = t + 2 * stride;
        if (t2 < ntiles) {
            stage(t2, (buf + 2) % NBUF);
            asm volatile("cp.async.wait_group 2;" ::: "memory");
        } else if (t + stride < ntiles) {
            asm volatile("cp.async.wait_group 1;" ::: "memory");
        } else {
            asm volatile("cp.async.wait_group 0;" ::: "memory");
        }
        __syncthreads();

        const __nv_bfloat16* Ab = Abf + buf * BM * ASB;
        const float* Ax = Axf + buf * BM * ASX;
        int r0l = wm * 16 + g;
        int r1l = r0l + 8;
        int r0g = row0 + r0l, r1g = row0 + r1l;

        float acc[4][4];
        #pragma unroll
        for (int j = 0; j < 4; j++)
            #pragma unroll
            for (int q = 0; q < 4; q++) acc[j][q] = 0.f;

        int arow = wm * 16 + (lane & 15);
        int acol = (lane >> 4) * 8;
        int brow = (lane & 7) + ((lane >> 3) & 1) * 8;
        int bcol = wn * 32 + ((lane >> 4) & 1) * 8;

        // ---- agg half: ldmatrix A fragments (k in [0,128)) ----
        #pragma unroll
        for (int kk = 0; kk < D; kk += 16) {
            unsigned a0, a1, a2, a3;
            unsigned ad = (unsigned)__cvta_generic_to_shared(
                &Ab[(size_t)arow * ASB + kk + acol]);
            asm volatile(
                "ldmatrix.sync.aligned.m8n8.x4.shared.b16 {%0,%1,%2,%3}, [%4];"
                : "=r"(a0), "=r"(a1), "=r"(a2), "=r"(a3) : "r"(ad));
            #pragma unroll
            for (int nt = 0; nt < 2; nt++) {
                unsigned b0, b1, b2, b3;
                unsigned bd = (unsigned)__cvta_generic_to_shared(
                    &Bs[(size_t)(kk + brow) * BS + bcol + nt * 16]);
                asm volatile(
                    "ldmatrix.sync.aligned.m8n8.x4.trans.shared.b16 {%0,%1,%2,%3}, [%4];"
                    : "=r"(b0), "=r"(b1), "=r"(b2), "=r"(b3) : "r"(bd));
                asm volatile(
                    "mma.sync.aligned.m16n8k16.row.col.f32.bf16.bf16.f32 "
                    "{%0,%1,%2,%3}, {%4,%5,%6,%7}, {%8,%9}, {%0,%1,%2,%3};"
                    : "+f"(acc[nt*2][0]), "+f"(acc[nt*2][1]),
                      "+f"(acc[nt*2][2]), "+f"(acc[nt*2][3])
                    : "r"(a0), "r"(a1), "r"(a2), "r"(a3), "r"(b0), "r"(b1));
                asm volatile(
                    "mma.sync.aligned.m16n8k16.row.col.f32.bf16.bf16.f32 "
                    "{%0,%1,%2,%3}, {%4,%5,%6,%7}, {%8,%9}, {%0,%1,%2,%3};"
                    : "+f"(acc[nt*2+1][0]), "+f"(acc[nt*2+1][1]),
                      "+f"(acc[nt*2+1][2]), "+f"(acc[nt*2+1][3])
                    : "r"(a0), "r"(a1), "r"(a2), "r"(a3), "r"(b2), "r"(b3));
            }
        }

        // ---- x half: LDS.64+cvt fragments (k in [128,256)) ----
        #pragma unroll
        for (int kk = D; kk < 256; kk += 16) {
            int kx = kk - D;
            float2 f0 = *reinterpret_cast<const float2*>(&Ax[r0l * ASX + kx + tg2]);
            float2 f1 = *reinterpret_cast<const float2*>(&Ax[r1l * ASX + kx + tg2]);
            float2 f2 = *reinterpret_cast<const float2*>(&Ax[r0l * ASX + kx + 8 + tg2]);
            float2 f3 = *reinterpret_cast<const float2*>(&Ax[r1l * ASX + kx + 8 + tg2]);
            __nv_bfloat162 h0 = __floats2bfloat162_rn(f0.x, f0.y);
            __nv_bfloat162 h1 = __floats2bfloat162_rn(f1.x, f1.y);
            __nv_bfloat162 h2 = __floats2bfloat162_rn(f2.x, f2.y);
            __nv_bfloat162 h3 = __floats2bfloat162_rn(f3.x, f3.y);
            unsigned a0 = *reinterpret_cast<unsigned*>(&h0);
            unsigned a1 = *reinterpret_cast<unsigned*>(&h1);
            unsigned a2 = *reinterpret_cast<unsigned*>(&h2);
            unsigned a3 = *reinterpret_cast<unsigned*>(&h3);
            #pragma unroll
            for (int nt = 0; nt < 2; nt++) {
                unsigned b0, b1, b2, b3;
                unsigned bd = (unsigned)__cvta_generic_to_shared(
                    &Bs[(size_t)(kk + brow) * BS + bcol + nt * 16]);
                asm volatile(
                    "ldmatrix.sync.aligned.m8n8.x4.trans.shared.b16 {%0,%1,%2,%3}, [%4];"
                    : "=r"(b0), "=r"(b1), "=r"(b2), "=r"(b3) : "r"(bd));
                asm volatile(
                    "mma.sync.aligned.m16n8k16.row.col.f32.bf16.bf16.f32 "
                    "{%0,%1,%2,%3}, {%4,%5,%6,%7}, {%8,%9}, {%0,%1,%2,%3};"
                    : "+f"(acc[nt*2][0]), "+f"(acc[nt*2][1]),
                      "+f"(acc[nt*2][2]), "+f"(acc[nt*2][3])
                    : "r"(a0), "r"(a1), "r"(a2), "r"(a3), "r"(b0), "r"(b1));
                asm volatile(
                    "mma.sync.aligned.m16n8k16.row.col.f32.bf16.bf16.f32 "
                    "{%0,%1,%2,%3}, {%4,%5,%6,%7}, {%8,%9}, {%0,%1,%2,%3};"
                    : "+f"(acc[nt*2+1][0]), "+f"(acc[nt*2+1][1]),
                      "+f"(acc[nt*2+1][2]), "+f"(acc[nt*2+1][3])
                    : "r"(a0), "r"(a1), "r"(a2), "r"(a3), "r"(b2), "r"(b3));
            }
        }

        // ---- epilogue: out = x(smem fp32) + res * tanh(acc) ----
        #pragma unroll
        for (int j = 0; j < 4; j++) {
            int col = wn * 32 + j * 8 + tg2;
            if (r0g < Nn) {
                float2 xv = *reinterpret_cast<const float2*>(&Ax[r0l * ASX + col]);
                float2 o;
                o.x = xv.x + resv * tanh_approx(acc[j][0]);
                o.y = xv.y + resv * tanh_approx(acc[j][1]);
                *reinterpret_cast<float2*>(out + (size_t)r0g * D + col) = o;
            }
            if (r1g < Nn) {
                float2 xv = *reinterpret_cast<const float2*>(&Ax[r1l * ASX + col]);
                float2 o;
                o.x = xv.x + resv * tanh_approx(acc[j][2]);
                o.y = xv.y + resv * tanh_approx(acc[j][3]);
                *reinterpret_cast<float2*>(out + (size_t)r1g * D + col) = o;
            }
        }
        __syncthreads();   // reads of buf complete before iter i+1 stages into it
        buf = (buf + 1) % NBUF;
    }
}

// ---------------------------------------------------------------------------
extern "C" void kernel_launch(void* const* d_in, const int* in_sizes, int n_in,
                              void* d_out, int out_size)
{
    const float* emb    = (const float*)d_in[0];
    const float* change = (const float*)d_in[1];
    const float* W1     = (const float*)d_in[2];
    const float* Wl1    = (const float*)d_in[3];
    const float* rel1   = (const float*)d_in[4];
    const float* W2     = (const float*)d_in[5];
    const float* Wl2    = (const float*)d_in[6];
    const float* rel2   = (const float*)d_in[7];
    const float* res    = (const float*)d_in[8];
    const float* jw     = (const float*)d_in[9];
    const float* ewj    = (const float*)d_in[10];
    const int*   ei     = (const int*)d_in[11];
    const int*   et     = (const int*)d_in[12];
    const int*   ej     = (const int*)d_in[13];

    int Nn = in_sizes[0] / D;
    int E  = in_sizes[12];
    int EJ = in_sizes[10];
    int ntiles = (Nn + BM - 1) / BM;
    int nscan = (Nn + SCAN_B - 1) / SCAN_B;

    float* out_change = (float*)d_out;
    float* out_dch    = (float*)d_out + (size_t)Nn * D;

    void *p_agg, *p_h, *p_cnt;
    cudaGetSymbolAddress(&p_agg, g_aggbf);
    cudaGetSymbolAddress(&p_h,   g_h);
    cudaGetSymbolAddress(&p_cnt, g_cnt);
    __nv_bfloat16* agg = (__nv_bfloat16*)p_agg;
    float* hbuf = (float*)p_h;

    cudaFuncSetAttribute(fused_gemm, cudaFuncAttributeMaxDynamicSharedMemorySize,
                         SMEM_BYTES);

    int convBlocks = (Nn + 7) / 8;

    // Strictly serial stream 0 — identical capture structure to passing R13.
    // ---- CSR build (shared by both layers) ----
    cudaMemsetAsync(p_cnt, 0, (size_t)Nn * sizeof(int), 0);
    deg_count<<<(E + 255) / 256, 256>>>(ei, E);
    scan1<<<nscan, SCAN_B>>>(Nn);
    scan2<<<1, 256>>>(nscan);
    scan3<<<(Nn + 255) / 256, 256>>>(Nn);
    csr_fill<<<(E + 255) / 256, 256>>>(ei, et, E);

    // Layer 1
    conv_gather<<<convBlocks, 256>>>(emb, rel1, agg, Nn);
    fused_gemm<<<152, 512, SMEM_BYTES>>>(emb, W1, Wl1, res, agg, hbuf, Nn, ntiles);

    // Layer 2 (agg buffer reused; stays L2-resident)
    conv_gather<<<convBlocks, 256>>>(hbuf, rel2, agg, Nn);
    fused_gemm<<<152, 512, SMEM_BYTES>>>(hbuf, W2, Wl2, res, agg, out_dch, Nn, ntiles);

    // Jump diffusion onto dchange + change passthrough, fused in one kernel
    // (disjoint outputs; streaming copy hides under scatter atomics' latency).
    jump_and_copy<<<2368, 256>>>(emb, ewj, jw, ej, out_dch,
                                 change, out_change, EJ, Nn, 512);
}

// round 15
// speedup vs baseline: 1.0026x; 1.0026x over previous
#include <cuda_runtime.h>
#include <cuda_bf16.h>
#include <math.h>

#define D 128
#define NMAX 100000
#define EMAX 620000
#define SCAN_B 512

// Static scratch (no allocations allowed)
__device__ __nv_bfloat16 g_aggbf[(size_t)NMAX * D];   // 25.6 MB
__device__ __nv_bfloat16 g_embbf[(size_t)NMAX * D];   // 25.6 MB
__device__ __nv_bfloat16 g_hbf  [(size_t)NMAX * D];   // 25.6 MB
__device__ float g_h[(size_t)NMAX * D];               // 51.2 MB (fp32 h)
__device__ int   g_cnt [NMAX];
__device__ int   g_ptr [NMAX];     // exclusive prefix; post-fill: ptr[i]=excl[i+1]
__device__ int   g_bsum[256];
__device__ int   g_boff[256];
__device__ unsigned g_ebuf[EMAX];  // src | (type<<17)

__device__ __forceinline__ void red_add_v4(float* p, float4 v) {
    asm volatile("red.global.add.v4.f32 [%0], {%1,%2,%3,%4};"
                 :: "l"(p), "f"(v.x), "f"(v.y), "f"(v.z), "f"(v.w) : "memory");
}

__device__ __forceinline__ float tanh_approx(float x) {
    float y;
    asm("tanh.approx.f32 %0, %1;" : "=f"(y) : "f"(x));
    return y;
}

__device__ __forceinline__ void cp16(unsigned saddr, const void* g, int srcsize) {
    asm volatile("cp.async.cg.shared.global [%0], [%1], 16, %2;"
                 :: "r"(saddr), "l"(g), "r"(srcsize));
}

// ---------------------------------------------------------------------------
// fp32 -> bf16 copy (for gather-side operands)
// ---------------------------------------------------------------------------
__global__ void to_bf16(const float* __restrict__ src,
                        __nv_bfloat16* __restrict__ dst, size_t n4)
{
    size_t stride = (size_t)gridDim.x * blockDim.x;
    for (size_t i = (size_t)blockIdx.x * blockDim.x + threadIdx.x; i < n4; i += stride) {
        float4 v = reinterpret_cast<const float4*>(src)[i];
        __nv_bfloat162 h01 = __floats2bfloat162_rn(v.x, v.y);
        __nv_bfloat162 h23 = __floats2bfloat162_rn(v.z, v.w);
        reinterpret_cast<uint2*>(dst)[i] =
            make_uint2(*reinterpret_cast<unsigned*>(&h01),
                       *reinterpret_cast<unsigned*>(&h23));
    }
}

// ---------------------------------------------------------------------------
// CSR build
// ---------------------------------------------------------------------------
__global__ void deg_count(const int* __restrict__ ei, int E) {
    int i = blockIdx.x * blockDim.x + threadIdx.x;
    if (i < E) atomicAdd(&g_cnt[__ldg(ei + E + i)], 1);
}

__global__ void scan1(int Nn) {
    __shared__ int warpsums[16];
    int i = blockIdx.x * SCAN_B + threadIdx.x;
    int lane = threadIdx.x & 31, w = threadIdx.x >> 5;
    int v = (i < Nn) ? g_cnt[i] : 0;
    int s = v;
    #pragma unroll
    for (int o = 1; o < 32; o <<= 1) {
        int t = __shfl_up_sync(~0u, s, o);
        if (lane >= o) s += t;
    }
    if (lane == 31) warpsums[w] = s;
    __syncthreads();
    if (w == 0) {
        int ws = (lane < 16) ? warpsums[lane] : 0;
        #pragma unroll
        for (int o = 1; o < 16; o <<= 1) {
            int t = __shfl_up_sync(~0u, ws, o);
            if (lane >= o) ws += t;
        }
        if (lane < 16) warpsums[lane] = ws;
    }
    __syncthreads();
    int base = (w > 0) ? warpsums[w - 1] : 0;
    if (i < Nn) g_ptr[i] = base + s - v;
    if (threadIdx.x == SCAN_B - 1) g_bsum[blockIdx.x] = base + s;
}

__global__ void scan2(int nb) {
    __shared__ int warpsums[8];
    int i = threadIdx.x;
    int lane = i & 31, w = i >> 5;
    int v = (i < nb) ? g_bsum[i] : 0;
    int s = v;
    #pragma unroll
    for (int o = 1; o < 32; o <<= 1) {
        int t = __shfl_up_sync(~0u, s, o);
        if (lane >= o) s += t;
    }
    if (lane == 31) warpsums[w] = s;
    __syncthreads();
    if (w == 0) {
        int ws = (lane < 8) ? warpsums[lane] : 0;
        #pragma unroll
        for (int o = 1; o < 8; o <<= 1) {
            int t = __shfl_up_sync(~0u, ws, o);
            if (lane >= o) ws += t;
        }
        if (lane < 8) warpsums[lane] = ws;
    }
    __syncthreads();
    int base = (w > 0) ? warpsums[w - 1] : 0;
    if (i < nb) g_boff[i] = base + s - v;
}

__global__ void scan3(int Nn) {
    int i = blockIdx.x * blockDim.x + threadIdx.x;
    if (i < Nn) g_ptr[i] += g_boff[i / SCAN_B];
}

__global__ void csr_fill(const int* __restrict__ ei, const int* __restrict__ et, int E) {
    int e = blockIdx.x * blockDim.x + threadIdx.x;
    if (e < E) {
        int dst = __ldg(ei + E + e);
        int p = atomicAdd(&g_ptr[dst], 1);
        g_ebuf[p] = (unsigned)__ldg(ei + e) | ((unsigned)__ldg(et + e) << 17);
    }
}

// ---------------------------------------------------------------------------
// Gather conv (bf16 x rows — halves the dominant gather traffic):
// warp per destination; lane owns 4 cols; writes NORMALIZED agg in bf16.
// ---------------------------------------------------------------------------
__global__ __launch_bounds__(256)
void conv_gather(const __nv_bfloat16* __restrict__ xbf,
                 const float* __restrict__ rel,
                 __nv_bfloat16* __restrict__ agg,
                 int Nn)
{
    int node = blockIdx.x * (blockDim.x >> 5) + (threadIdx.x >> 5);
    if (node >= Nn) return;
    int lane = threadIdx.x & 31;
    int beg = (node == 0) ? 0 : __ldg(&g_ptr[node - 1]);
    int end = __ldg(&g_ptr[node]);
    float4 acc = make_float4(0.f, 0.f, 0.f, 0.f);
    for (int i = beg; i < end; i++) {
        unsigned e = __ldg(&g_ebuf[i]);
        int src = e & 0x1FFFF;
        int typ = e >> 17;
        uint2 xp = reinterpret_cast<const uint2*>(xbf + (size_t)src * D)[lane];
        float2 x01 = __bfloat1622float2(*reinterpret_cast<__nv_bfloat162*>(&xp.x));
        float2 x23 = __bfloat1622float2(*reinterpret_cast<__nv_bfloat162*>(&xp.y));
        float4 rv = reinterpret_cast<const float4*>(rel + (size_t)typ * D)[lane];
        acc.x += x01.x * rv.x; acc.y += x01.y * rv.y;
        acc.z += x23.x * rv.z; acc.w += x23.y * rv.w;
    }
    float inv = 1.0f / fmaxf((float)(end - beg), 1.0f);
    __nv_bfloat162 p01 = __floats2bfloat162_rn(acc.x * inv, acc.y * inv);
    __nv_bfloat162 p23 = __floats2bfloat162_rn(acc.z * inv, acc.w * inv);
    reinterpret_cast<uint2*>(agg + (size_t)node * D)[lane] =
        make_uint2(*reinterpret_cast<unsigned*>(&p01),
                   *reinterpret_cast<unsigned*>(&p23));
}

// ---------------------------------------------------------------------------
// Jump scatter (fp32 emb — bf16 here would push rel_err near the gate)
// ---------------------------------------------------------------------------
__global__ __launch_bounds__(256)
void jump_scatter(const float* __restrict__ emb,
                  const float* __restrict__ ew,
                  const float* __restrict__ jwp,
                  const int* __restrict__ ej,
                  float* __restrict__ out, int EJ)
{
    float jw = __ldg(jwp);
    int lane = threadIdx.x & 31;
    int warp = blockIdx.x * (blockDim.x >> 5) + (threadIdx.x >> 5);
    int nwarps = gridDim.x * (blockDim.x >> 5);
    for (int e = warp; e < EJ; e += nwarps) {
        int src = __ldg(ej + e);
        int dst = __ldg(ej + EJ + e);
        float w = jw * __ldg(ew + e);
        float4 v = reinterpret_cast<const float4*>(emb + (size_t)src * D)[lane];
        v.x *= w; v.y *= w; v.z *= w; v.w *= w;
        red_add_v4(out + (size_t)dst * D + lane * 4, v);
    }
}

// ---------------------------------------------------------------------------
// Pipelined fused GEMM (triple-buffered, all-bf16 A, uniform ldmatrix):
//   out = x + res * tanh( aggbf @ Wa + xbf @ Wx )        (x fp32 from global)
// A row = [agg 128 bf16 | x 128 bf16] + pad; staged entirely via cp.async.
// Epilogue reads exact fp32 x from GLOBAL; optionally emits bf16 copy of out.
// 512 threads = 16 warps (4 m x 4 n), 1 CTA/SM, smem ~167KB.
// ---------------------------------------------------------------------------
#define BM 64
#define ASA 264                               // bf16 per A row (256 + 8 pad)
#define BS  136
#define NBUF 3
#define ABF_BYTES (BM * ASA * 2)              // 33792 per buf
#define SMEM_B_OFF (NBUF * ABF_BYTES)         // 101376
#define SMEM_BYTES (SMEM_B_OFF + 256 * BS * 2)   // 171008

__global__ __launch_bounds__(512, 1)
void fused_gemm(const float* __restrict__ x,            // fp32, epilogue only
                const __nv_bfloat16* __restrict__ xbf,  // bf16, MMA operand
                const float* __restrict__ Wa,
                const float* __restrict__ Wx,
                const float* __restrict__ resp,
                const __nv_bfloat16* __restrict__ aggbf,
                float* __restrict__ out,
                __nv_bfloat16* __restrict__ outbf,      // nullable bf16 copy
                int Nn, int ntiles)
{
    extern __shared__ char smraw[];
    __nv_bfloat16* Abf = reinterpret_cast<__nv_bfloat16*>(smraw);   // [3][BM*ASA]
    __nv_bfloat16* Bs = reinterpret_cast<__nv_bfloat16*>(smraw + SMEM_B_OFF);

    int tid  = threadIdx.x;
    int lane = tid & 31;
    int wid  = tid >> 5;
    int wm   = wid & 3;
    int wn   = wid >> 2;
    int g    = lane >> 2;
    int tg2  = (lane & 3) * 2;

    unsigned sAbf = (unsigned)__cvta_generic_to_shared(Abf);

    // ---- stage weights once (bf16) ----
    for (int idx = tid; idx < 256 * D / 4; idx += 512) {
        int k  = idx >> 5;
        int c4 = (idx & 31) * 4;
        const float* src = (k < D) ? (Wa + (size_t)k * D) : (Wx + (size_t)(k - D) * D);
        float4 v = *reinterpret_cast<const float4*>(src + c4);
        *reinterpret_cast<__nv_bfloat162*>(&Bs[k * BS + c4])     = __floats2bfloat162_rn(v.x, v.y);
        *reinterpret_cast<__nv_bfloat162*>(&Bs[k * BS + c4 + 2]) = __floats2bfloat162_rn(v.z, v.w);
    }

    float resv = __ldg(resp);
    int stride = gridDim.x;

    // staging: 32 16B-chunks per row (16 agg + 16 xbf), 64 rows, all bf16
    auto stage = [&](int tile, int buf) {
        int row0 = tile * BM;
        unsigned b = sAbf + (unsigned)buf * ABF_BYTES;
        for (int i = tid; i < BM * 32; i += 512) {
            int r = i >> 5, c = i & 31;
            int row = row0 + r;
            int ok = (row < Nn) ? 16 : 0;
            const __nv_bfloat16* src = (c < 16)
                ? (aggbf + (size_t)row * D + c * 8)
                : (xbf   + (size_t)row * D + (c - 16) * 8);
            cp16(b + (unsigned)(r * ASA + c * 8) * 2, src, ok);
        }
        asm volatile("cp.async.commit_group;" ::: "memory");
    };

    int t0 = blockIdx.x;
    stage(t0, 0);
    if (t0 + stride < ntiles) stage(t0 + stride, 1);

    int buf = 0;
    for (int t = t0; t < ntiles; t += stride) {
        int row0 = t * BM;
        int t2 = t + 2 * stride;
        if (t2 < ntiles) {
            stage(t2, (buf + 2) % NBUF);
            asm volatile("cp.async.wait_group 2;" ::: "memory");
        } else if (t + stride < ntiles) {
            asm volatile("cp.async.wait_group 1;" ::: "memory");
        } else {
            asm volatile("cp.async.wait_group 0;" ::: "memory");
        }
        __syncthreads();

        const __nv_bfloat16* Ab = Abf + buf * BM * ASA;
        int r0l = wm * 16 + g;
        int r1l = r0l + 8;
        int r0g = row0 + r0l, r1g = row0 + r1l;

        float acc[4][4];
        #pragma unroll
        for (int j = 0; j < 4; j++)
            #pragma unroll
            for (int q = 0; q < 4; q++) acc[j][q] = 0.f;

        int arow = wm * 16 + (lane & 15);
        int acol = (lane >> 4) * 8;
        int brow = (lane & 7) + ((lane >> 3) & 1) * 8;
        int bcol = wn * 32 + ((lane >> 4) & 1) * 8;

        // ---- uniform ldmatrix A over full K=256 ----
        #pragma unroll
        for (int kk = 0; kk < 256; kk += 16) {
            unsigned a0, a1, a2, a3;
            unsigned ad = (unsigned)__cvta_generic_to_shared(
                &Ab[(size_t)arow * ASA + kk + acol]);
            asm volatile(
                "ldmatrix.sync.aligned.m8n8.x4.shared.b16 {%0,%1,%2,%3}, [%4];"
                : "=r"(a0), "=r"(a1), "=r"(a2), "=r"(a3) : "r"(ad));
            #pragma unroll
            for (int nt = 0; nt < 2; nt++) {
                unsigned b0, b1, b2, b3;
                unsigned bd = (unsigned)__cvta_generic_to_shared(
                    &Bs[(size_t)(kk + brow) * BS + bcol + nt * 16]);
                asm volatile(
                    "ldmatrix.sync.aligned.m8n8.x4.trans.shared.b16 {%0,%1,%2,%3}, [%4];"
                    : "=r"(b0), "=r"(b1), "=r"(b2), "=r"(b3) : "r"(bd));
                asm volatile(
                    "mma.sync.aligned.m16n8k16.row.col.f32.bf16.bf16.f32 "
                    "{%0,%1,%2,%3}, {%4,%5,%6,%7}, {%8,%9}, {%0,%1,%2,%3};"
                    : "+f"(acc[nt*2][0]), "+f"(acc[nt*2][1]),
                      "+f"(acc[nt*2][2]), "+f"(acc[nt*2][3])
                    : "r"(a0), "r"(a1), "r"(a2), "r"(a3), "r"(b0), "r"(b1));
                asm volatile(
                    "mma.sync.aligned.m16n8k16.row.col.f32.bf16.bf16.f32 "
                    "{%0,%1,%2,%3}, {%4,%5,%6,%7}, {%8,%9}, {%0,%1,%2,%3};"
                    : "+f"(acc[nt*2+1][0]), "+f"(acc[nt*2+1][1]),
                      "+f"(acc[nt*2+1][2]), "+f"(acc[nt*2+1][3])
                    : "r"(a0), "r"(a1), "r"(a2), "r"(a3), "r"(b2), "r"(b3));
            }
        }

        // ---- epilogue: out = x(fp32, global) + res * tanh(acc) [+ bf16 copy] ----
        #pragma unroll
        for (int j = 0; j < 4; j++) {
            int col = wn * 32 + j * 8 + tg2;
            if (r0g < Nn) {
                float2 xv = *reinterpret_cast<const float2*>(x + (size_t)r0g * D + col);
                float2 o;
                o.x = xv.x + resv * tanh_approx(acc[j][0]);
                o.y = xv.y + resv * tanh_approx(acc[j][1]);
                *reinterpret_cast<float2*>(out + (size_t)r0g * D + col) = o;
                if (outbf) {
                    __nv_bfloat162 ob = __floats2bfloat162_rn(o.x, o.y);
                    *reinterpret_cast<unsigned*>(outbf + (size_t)r0g * D + col) =
                        *reinterpret_cast<unsigned*>(&ob);
                }
            }
            if (r1g < Nn) {
                float2 xv = *reinterpret_cast<const float2*>(x + (size_t)r1g * D + col);
                float2 o;
                o.x = xv.x + resv * tanh_approx(acc[j][2]);
                o.y = xv.y + resv * tanh_approx(acc[j][3]);
                *reinterpret_cast<float2*>(out + (size_t)r1g * D + col) = o;
                if (outbf) {
                    __nv_bfloat162 ob = __floats2bfloat162_rn(o.x, o.y);
                    *reinterpret_cast<unsigned*>(outbf + (size_t)r1g * D + col) =
                        *reinterpret_cast<unsigned*>(&ob);
                }
            }
        }
        __syncthreads();   // reads of buf complete before iter i+1 stages into it
        buf = (buf + 1) % NBUF;
    }
}

// ---------------------------------------------------------------------------
extern "C" void kernel_launch(void* const* d_in, const int* in_sizes, int n_in,
                              void* d_out, int out_size)
{
    const float* emb    = (const float*)d_in[0];
    const float* change = (const float*)d_in[1];
    const float* W1     = (const float*)d_in[2];
    const float* Wl1    = (const float*)d_in[3];
    const float* rel1   = (const float*)d_in[4];
    const float* W2     = (const float*)d_in[5];
    const float* Wl2    = (const float*)d_in[6];
    const float* rel2   = (const float*)d_in[7];
    const float* res    = (const float*)d_in[8];
    const float* jw     = (const float*)d_in[9];
    const float* ewj    = (const float*)d_in[10];
    const int*   ei     = (const int*)d_in[11];
    const int*   et     = (const int*)d_in[12];
    const int*   ej     = (const int*)d_in[13];

    int Nn = in_sizes[0] / D;
    int E  = in_sizes[12];
    int EJ = in_sizes[10];
    int ntiles = (Nn + BM - 1) / BM;
    int nscan = (Nn + SCAN_B - 1) / SCAN_B;
    size_t rowBytes = (size_t)Nn * D * sizeof(float);

    float* out_change = (float*)d_out;
    float* out_dch    = (float*)d_out + (size_t)Nn * D;

    void *p_agg, *p_embbf, *p_hbf, *p_h, *p_cnt;
    cudaGetSymbolAddress(&p_agg,   g_aggbf);
    cudaGetSymbolAddress(&p_embbf, g_embbf);
    cudaGetSymbolAddress(&p_hbf,   g_hbf);
    cudaGetSymbolAddress(&p_h,     g_h);
    cudaGetSymbolAddress(&p_cnt,   g_cnt);
    __nv_bfloat16* agg   = (__nv_bfloat16*)p_agg;
    __nv_bfloat16* embbf = (__nv_bfloat16*)p_embbf;
    __nv_bfloat16* hbf   = (__nv_bfloat16*)p_hbf;
    float* hbuf = (float*)p_h;

    cudaFuncSetAttribute(fused_gemm, cudaFuncAttributeMaxDynamicSharedMemorySize,
                         SMEM_BYTES);

    int convBlocks = (Nn + 7) / 8;

    // Strictly serial stream 0 — capture structure proven in R11/R13.
    // ---- CSR build + emb bf16 prep ----
    cudaMemsetAsync(p_cnt, 0, (size_t)Nn * sizeof(int), 0);
    deg_count<<<(E + 255) / 256, 256>>>(ei, E);
    to_bf16<<<1024, 256>>>(emb, embbf, (size_t)Nn * D / 4);
    scan1<<<nscan, SCAN_B>>>(Nn);
    scan2<<<1, 256>>>(nscan);
    scan3<<<(Nn + 255) / 256, 256>>>(Nn);
    csr_fill<<<(E + 255) / 256, 256>>>(ei, et, E);

    // Layer 1: conv gathers bf16 emb; gemm emits fp32 h + bf16 h copy
    conv_gather<<<convBlocks, 256>>>(embbf, rel1, agg, Nn);
    fused_gemm<<<152, 512, SMEM_BYTES>>>(emb, embbf, W1, Wl1, res, agg,
                                         hbuf, hbf, Nn, ntiles);

    // Layer 2: conv gathers bf16 h; gemm writes dchange (no bf16 copy)
    conv_gather<<<convBlocks, 256>>>(hbf, rel2, agg, Nn);
    fused_gemm<<<152, 512, SMEM_BYTES>>>(hbuf, hbf, W2, Wl2, res, agg,
                                         out_dch, (__nv_bfloat16*)nullptr,
                                         Nn, ntiles);

    // Jump diffusion accumulates directly onto dchange (fp32 emb)
    jump_scatter<<<2368, 256>>>(emb, ewj, jw, ej, out_dch, EJ);

    // change passthrough
    cudaMemcpyAsync(out_change, change, rowBytes, cudaMemcpyDeviceToDevice, 0);
}

// round 16
// speedup vs baseline: 1.0081x; 1.0055x over previous
#include <cuda_runtime.h>
#include <cuda_bf16.h>
#include <math.h>

#define D 128
#define NMAX 100000
#define EMAX 620000
#define SCAN_B 512

// Static scratch (no allocations allowed)
__device__ __nv_bfloat16 g_aggbf[(size_t)NMAX * D];   // 25.6 MB, both layers
__device__ __nv_bfloat16 g_hbf  [(size_t)NMAX * D];   // 25.6 MB (bf16 h for conv2)
__device__ float g_h[(size_t)NMAX * D];               // 51.2 MB (fp32 h)
__device__ int   g_cnt [NMAX];
__device__ int   g_ptr [NMAX];     // exclusive prefix; post-fill: ptr[i]=excl[i+1]
__device__ int   g_bsum[256];
__device__ int   g_boff[256];
__device__ unsigned g_ebuf[EMAX];  // src | (type<<17)

__device__ __forceinline__ void red_add_v4(float* p, float4 v) {
    asm volatile("red.global.add.v4.f32 [%0], {%1,%2,%3,%4};"
                 :: "l"(p), "f"(v.x), "f"(v.y), "f"(v.z), "f"(v.w) : "memory");
}

__device__ __forceinline__ float tanh_approx(float x) {
    float y;
    asm("tanh.approx.f32 %0, %1;" : "=f"(y) : "f"(x));
    return y;
}

__device__ __forceinline__ void cp16(unsigned saddr, const void* g, int srcsize) {
    asm volatile("cp.async.cg.shared.global [%0], [%1], 16, %2;"
                 :: "r"(saddr), "l"(g), "r"(srcsize));
}

// ---------------------------------------------------------------------------
// CSR build
// ---------------------------------------------------------------------------
__global__ void deg_count(const int* __restrict__ ei, int E) {
    int i = blockIdx.x * blockDim.x + threadIdx.x;
    if (i < E) atomicAdd(&g_cnt[__ldg(ei + E + i)], 1);
}

__global__ void scan1(int Nn) {
    __shared__ int warpsums[16];
    int i = blockIdx.x * SCAN_B + threadIdx.x;
    int lane = threadIdx.x & 31, w = threadIdx.x >> 5;
    int v = (i < Nn) ? g_cnt[i] : 0;
    int s = v;
    #pragma unroll
    for (int o = 1; o < 32; o <<= 1) {
        int t = __shfl_up_sync(~0u, s, o);
        if (lane >= o) s += t;
    }
    if (lane == 31) warpsums[w] = s;
    __syncthreads();
    if (w == 0) {
        int ws = (lane < 16) ? warpsums[lane] : 0;
        #pragma unroll
        for (int o = 1; o < 16; o <<= 1) {
            int t = __shfl_up_sync(~0u, ws, o);
            if (lane >= o) ws += t;
        }
        if (lane < 16) warpsums[lane] = ws;
    }
    __syncthreads();
    int base = (w > 0) ? warpsums[w - 1] : 0;
    if (i < Nn) g_ptr[i] = base + s - v;
    if (threadIdx.x == SCAN_B - 1) g_bsum[blockIdx.x] = base + s;
}

// Parallel block-scan over per-block sums (nb <= 256); one 256-thread block.
__global__ void scan2(int nb) {
    __shared__ int warpsums[8];
    int i = threadIdx.x;
    int lane = i & 31, w = i >> 5;
    int v = (i < nb) ? g_bsum[i] : 0;
    int s = v;
    #pragma unroll
    for (int o = 1; o < 32; o <<= 1) {
        int t = __shfl_up_sync(~0u, s, o);
        if (lane >= o) s += t;
    }
    if (lane == 31) warpsums[w] = s;
    __syncthreads();
    if (w == 0) {
        int ws = (lane < 8) ? warpsums[lane] : 0;
        #pragma unroll
        for (int o = 1; o < 8; o <<= 1) {
            int t = __shfl_up_sync(~0u, ws, o);
            if (lane >= o) ws += t;
        }
        if (lane < 8) warpsums[lane] = ws;
    }
    __syncthreads();
    int base = (w > 0) ? warpsums[w - 1] : 0;
    if (i < nb) g_boff[i] = base + s - v;   // exclusive prefix
}

__global__ void scan3(int Nn) {
    int i = blockIdx.x * blockDim.x + threadIdx.x;
    if (i < Nn) g_ptr[i] += g_boff[i / SCAN_B];
}

// Bumps g_ptr[dst] itself: afterwards ptr[i] == exclusive_prefix[i+1].
__global__ void csr_fill(const int* __restrict__ ei, const int* __restrict__ et, int E) {
    int e = blockIdx.x * blockDim.x + threadIdx.x;
    if (e < E) {
        int dst = __ldg(ei + E + e);
        int p = atomicAdd(&g_ptr[dst], 1);
        g_ebuf[p] = (unsigned)__ldg(ei + e) | ((unsigned)__ldg(et + e) << 17);
    }
}

// ---------------------------------------------------------------------------
// Gather conv (fp32 x rows): warp per destination; writes NORMALIZED bf16 agg.
// ---------------------------------------------------------------------------
__global__ __launch_bounds__(256)
void conv_gather_f32(const float* __restrict__ x,
                     const float* __restrict__ rel,
                     __nv_bfloat16* __restrict__ agg,
                     int Nn)
{
    int node = blockIdx.x * (blockDim.x >> 5) + (threadIdx.x >> 5);
    if (node >= Nn) return;
    int lane = threadIdx.x & 31;
    int beg = (node == 0) ? 0 : __ldg(&g_ptr[node - 1]);
    int end = __ldg(&g_ptr[node]);
    float4 acc = make_float4(0.f, 0.f, 0.f, 0.f);
    for (int i = beg; i < end; i++) {
        unsigned e = __ldg(&g_ebuf[i]);
        int src = e & 0x1FFFF;
        int typ = e >> 17;
        float4 xv = reinterpret_cast<const float4*>(x   + (size_t)src * D)[lane];
        float4 rv = reinterpret_cast<const float4*>(rel + (size_t)typ * D)[lane];
        acc.x += xv.x * rv.x; acc.y += xv.y * rv.y;
        acc.z += xv.z * rv.z; acc.w += xv.w * rv.w;
    }
    float inv = 1.0f / fmaxf((float)(end - beg), 1.0f);
    __nv_bfloat162 p01 = __floats2bfloat162_rn(acc.x * inv, acc.y * inv);
    __nv_bfloat162 p23 = __floats2bfloat162_rn(acc.z * inv, acc.w * inv);
    reinterpret_cast<uint2*>(agg + (size_t)node * D)[lane] =
        make_uint2(*reinterpret_cast<unsigned*>(&p01),
                   *reinterpret_cast<unsigned*>(&p23));
}

// ---------------------------------------------------------------------------
// Gather conv (bf16 x rows — halves the dominant LTS gather traffic).
// ---------------------------------------------------------------------------
__global__ __launch_bounds__(256)
void conv_gather_bf16(const __nv_bfloat16* __restrict__ xbf,
                      const float* __restrict__ rel,
                      __nv_bfloat16* __restrict__ agg,
                      int Nn)
{
    int node = blockIdx.x * (blockDim.x >> 5) + (threadIdx.x >> 5);
    if (node >= Nn) return;
    int lane = threadIdx.x & 31;
    int beg = (node == 0) ? 0 : __ldg(&g_ptr[node - 1]);
    int end = __ldg(&g_ptr[node]);
    float4 acc = make_float4(0.f, 0.f, 0.f, 0.f);
    for (int i = beg; i < end; i++) {
        unsigned e = __ldg(&g_ebuf[i]);
        int src = e & 0x1FFFF;
        int typ = e >> 17;
        uint2 xp = reinterpret_cast<const uint2*>(xbf + (size_t)src * D)[lane];
        float2 x01 = __bfloat1622float2(*reinterpret_cast<__nv_bfloat162*>(&xp.x));
        float2 x23 = __bfloat1622float2(*reinterpret_cast<__nv_bfloat162*>(&xp.y));
        float4 rv = reinterpret_cast<const float4*>(rel + (size_t)typ * D)[lane];
        acc.x += x01.x * rv.x; acc.y += x01.y * rv.y;
        acc.z += x23.x * rv.z; acc.w += x23.y * rv.w;
    }
    float inv = 1.0f / fmaxf((float)(end - beg), 1.0f);
    __nv_bfloat162 p01 = __floats2bfloat162_rn(acc.x * inv, acc.y * inv);
    __nv_bfloat162 p23 = __floats2bfloat162_rn(acc.z * inv, acc.w * inv);
    reinterpret_cast<uint2*>(agg + (size_t)node * D)[lane] =
        make_uint2(*reinterpret_cast<unsigned*>(&p01),
                   *reinterpret_cast<unsigned*>(&p23));
}

// ---------------------------------------------------------------------------
// Jump scatter: out[dst] += jw * ew[e] * emb[src]  (fp32; LTS-bound)
// ---------------------------------------------------------------------------
__global__ __launch_bounds__(256)
void jump_scatter(const float* __restrict__ emb,
                  const float* __restrict__ ew,
                  const float* __restrict__ jwp,
                  const int* __restrict__ ej,
                  float* __restrict__ out, int EJ)
{
    float jw = __ldg(jwp);
    int lane = threadIdx.x & 31;
    int warp = blockIdx.x * (blockDim.x >> 5) + (threadIdx.x >> 5);
    int nwarps = gridDim.x * (blockDim.x >> 5);
    for (int e = warp; e < EJ; e += nwarps) {
        int src = __ldg(ej + e);
        int dst = __ldg(ej + EJ + e);
        float w = jw * __ldg(ew + e);
        float4 v = reinterpret_cast<const float4*>(emb + (size_t)src * D)[lane];
        v.x *= w; v.y *= w; v.z *= w; v.w *= w;
        red_add_v4(out + (size_t)dst * D + lane * 4, v);
    }
}

// ---------------------------------------------------------------------------
// Pipelined fused GEMM (TRIPLE-buffered, prefetch distance 2):
//   out = x + res * tanh( aggbf @ Wa + x @ Wx )   [+ optional bf16 copy of out]
// A split: agg half staged bf16 via cp.async (ldmatrix fragments),
//          x half staged fp32 (LDS+cvt fragments; epilogue reads it fp32).
// 512 threads = 16 warps (4 m x 4 n), 1 CTA/SM, smem ~218KB.
// ---------------------------------------------------------------------------
#define BM 64
#define ASB 136                               // bf16 per agg row (272B, padded)
#define ASX 132                               // fp32 per x row (528B, padded)
#define BS  136
#define NBUF 3
#define ABF_BYTES (BM * ASB * 2)              // 17408 per buf
#define AXF_BYTES (BM * ASX * 4)              // 33792 per buf
#define SMEM_B_OFF (NBUF * (ABF_BYTES + AXF_BYTES))   // 153600
#define SMEM_BYTES (SMEM_B_OFF + 256 * BS * 2)        // 223232

__global__ __launch_bounds__(512, 1)
void fused_gemm(const float* __restrict__ x,
                const float* __restrict__ Wa,
                const float* __restrict__ Wx,
                const float* __restrict__ resp,
                const __nv_bfloat16* __restrict__ aggbf,
                float* __restrict__ out,
                __nv_bfloat16* __restrict__ outbf,   // nullable bf16 copy of out
                int Nn, int ntiles)
{
    extern __shared__ char smraw[];
    __nv_bfloat16* Abf = reinterpret_cast<__nv_bfloat16*>(smraw);             // [3][BM*ASB]
    float* Axf = reinterpret_cast<float*>(smraw + NBUF * ABF_BYTES);          // [3][BM*ASX]
    __nv_bfloat16* Bs = reinterpret_cast<__nv_bfloat16*>(smraw + SMEM_B_OFF);

    int tid  = threadIdx.x;
    int lane = tid & 31;
    int wid  = tid >> 5;
    int wm   = wid & 3;
    int wn   = wid >> 2;
    int g    = lane >> 2;
    int tg2  = (lane & 3) * 2;

    unsigned sAbf = (unsigned)__cvta_generic_to_shared(Abf);
    unsigned sAxf = (unsigned)__cvta_generic_to_shared(Axf);

    // ---- stage weights once (bf16) ----
    for (int idx = tid; idx < 256 * D / 4; idx += 512) {
        int k  = idx >> 5;
        int c4 = (idx & 31) * 4;
        const float* src = (k < D) ? (Wa + (size_t)k * D) : (Wx + (size_t)(k - D) * D);
        float4 v = *reinterpret_cast<const float4*>(src + c4);
        *reinterpret_cast<__nv_bfloat162*>(&Bs[k * BS + c4])     = __floats2bfloat162_rn(v.x, v.y);
        *reinterpret_cast<__nv_bfloat162*>(&Bs[k * BS + c4 + 2]) = __floats2bfloat162_rn(v.z, v.w);
    }

    float resv = __ldg(resp);
    int stride = gridDim.x;

    // staging: 48 16B-chunks per row (16 agg-bf16 + 32 x-fp32), 64 rows
    auto stage = [&](int tile, int buf) {
        int row0 = tile * BM;
        unsigned b_bf = sAbf + (unsigned)buf * ABF_BYTES;
        unsigned b_xf = sAxf + (unsigned)buf * AXF_BYTES;
        for (int i = tid; i < BM * 48; i += 512) {
            int r = i / 48, c = i % 48;
            int row = row0 + r;
            int ok = (row < Nn) ? 16 : 0;
            if (c < 16) {
                cp16(b_bf + (unsigned)(r * ASB + c * 8) * 2,
                     aggbf + (size_t)row * D + c * 8, ok);
            } else {
                int cx = c - 16;
                cp16(b_xf + (unsigned)(r * ASX + cx * 4) * 4,
                     x + (size_t)row * D + cx * 4, ok);
            }
        }
        asm volatile("cp.async.commit_group;" ::: "memory");
    };

    int t0 = blockIdx.x;
    stage(t0, 0);
    if (t0 + stride < ntiles) stage(t0 + stride, 1);

    int buf = 0;
    for (int t = t0; t < ntiles; t += stride) {
        int row0 = t * BM;
        // prefetch distance 2, then wait with EXACT pending count for buf
        int t2 = t + 2 * stride;
        if (t2 < ntiles) {
            stage(t2, (buf + 2) % NBUF);
            asm volatile("cp.async.wait_group 2;" ::: "memory");
        } else if (t + stride < ntiles) {
            asm volatile("cp.async.wait_group 1;" ::: "memory");
        } else {
            asm volatile("cp.async.wait_group 0;" ::: "memory");
        }
        __syncthreads();

        const __nv_bfloat16* Ab = Abf + buf * BM * ASB;
        const float* Ax = Axf + buf * BM * ASX;
        int r0l = wm * 16 + g;
        int r1l = r0l + 8;
        int r0g = row0 + r0l, r1g = row0 + r1l;

        float acc[4][4];
        #pragma unroll
        for (int j = 0; j < 4; j++)
            #pragma unroll
            for (int q = 0; q < 4; q++) acc[j][q] = 0.f;

        int arow = wm * 16 + (lane & 15);
        int acol = (lane >> 4) * 8;
        int brow = (lane & 7) + ((lane >> 3) & 1) * 8;
        int bcol = wn * 32 + ((lane >> 4) & 1) * 8;

        // ---- agg half: ldmatrix A fragments (k in [0,128)) ----
        #pragma unroll
        for (int kk = 0; kk < D; kk += 16) {
            unsigned a0, a1, a2, a3;
            unsigned ad = (unsigned)__cvta_generic_to_shared(
                &Ab[(size_t)arow * ASB + kk + acol]);
            asm volatile(
                "ldmatrix.sync.aligned.m8n8.x4.shared.b16 {%0,%1,%2,%3}, [%4];"
                : "=r"(a0), "=r"(a1), "=r"(a2), "=r"(a3) : "r"(ad));
            #pragma unroll
            for (int nt = 0; nt < 2; nt++) {
                unsigned b0, b1, b2, b3;
                unsigned bd = (unsigned)__cvta_generic_to_shared(
                    &Bs[(size_t)(kk + brow) * BS + bcol + nt * 16]);
                asm volatile(
                    "ldmatrix.sync.aligned.m8n8.x4.trans.shared.b16 {%0,%1,%2,%3}, [%4];"
                    : "=r"(b0), "=r"(b1), "=r"(b2), "=r"(b3) : "r"(bd));
                asm volatile(
                    "mma.sync.aligned.m16n8k16.row.col.f32.bf16.bf16.f32 "
                    "{%0,%1,%2,%3}, {%4,%5,%6,%7}, {%8,%9}, {%0,%1,%2,%3};"
                    : "+f"(acc[nt*2][0]), "+f"(acc[nt*2][1]),
                      "+f"(acc[nt*2][2]), "+f"(acc[nt*2][3])
                    : "r"(a0), "r"(a1), "r"(a2), "r"(a3), "r"(b0), "r"(b1));
                asm volatile(
                    "mma.sync.aligned.m16n8k16.row.col.f32.bf16.bf16.f32 "
                    "{%0,%1,%2,%3}, {%4,%5,%6,%7}, {%8,%9}, {%0,%1,%2,%3};"
                    : "+f"(acc[nt*2+1][0]), "+f"(acc[nt*2+1][1]),
                      "+f"(acc[nt*2+1][2]), "+f"(acc[nt*2+1][3])
                    : "r"(a0), "r"(a1), "r"(a2), "r"(a3), "r"(b2), "r"(b3));
            }
        }

        // ---- x half: LDS.64+cvt fragments (k in [128,256)) ----
        #pragma unroll
        for (int kk = D; kk < 256; kk += 16) {
            int kx = kk - D;
            float2 f0 = *reinterpret_cast<const float2*>(&Ax[r0l * ASX + kx + tg2]);
            float2 f1 = *reinterpret_cast<const float2*>(&Ax[r1l * ASX + kx + tg2]);
            float2 f2 = *reinterpret_cast<const float2*>(&Ax[r0l * ASX + kx + 8 + tg2]);
            float2 f3 = *reinterpret_cast<const float2*>(&Ax[r1l * ASX + kx + 8 + tg2]);
            __nv_bfloat162 h0 = __floats2bfloat162_rn(f0.x, f0.y);
            __nv_bfloat162 h1 = __floats2bfloat162_rn(f1.x, f1.y);
            __nv_bfloat162 h2 = __floats2bfloat162_rn(f2.x, f2.y);
            __nv_bfloat162 h3 = __floats2bfloat162_rn(f3.x, f3.y);
            unsigned a0 = *reinterpret_cast<unsigned*>(&h0);
            unsigned a1 = *reinterpret_cast<unsigned*>(&h1);
            unsigned a2 = *reinterpret_cast<unsigned*>(&h2);
            unsigned a3 = *reinterpret_cast<unsigned*>(&h3);
            #pragma unroll
            for (int nt = 0; nt < 2; nt++) {
                unsigned b0, b1, b2, b3;
                unsigned bd = (unsigned)__cvta_generic_to_shared(
                    &Bs[(size_t)(kk + brow) * BS + bcol + nt * 16]);
                asm volatile(
                    "ldmatrix.sync.aligned.m8n8.x4.trans.shared.b16 {%0,%1,%2,%3}, [%4];"
                    : "=r"(b0), "=r"(b1), "=r"(b2), "=r"(b3) : "r"(bd));
                asm volatile(
                    "mma.sync.aligned.m16n8k16.row.col.f32.bf16.bf16.f32 "
                    "{%0,%1,%2,%3}, {%4,%5,%6,%7}, {%8,%9}, {%0,%1,%2,%3};"
                    : "+f"(acc[nt*2][0]), "+f"(acc[nt*2][1]),
                      "+f"(acc[nt*2][2]), "+f"(acc[nt*2][3])
                    : "r"(a0), "r"(a1), "r"(a2), "r"(a3), "r"(b0), "r"(b1));
                asm volatile(
                    "mma.sync.aligned.m16n8k16.row.col.f32.bf16.bf16.f32 "
                    "{%0,%1,%2,%3}, {%4,%5,%6,%7}, {%8,%9}, {%0,%1,%2,%3};"
                    : "+f"(acc[nt*2+1][0]), "+f"(acc[nt*2+1][1]),
                      "+f"(acc[nt*2+1][2]), "+f"(acc[nt*2+1][3])
                    : "r"(a0), "r"(a1), "r"(a2), "r"(a3), "r"(b2), "r"(b3));
            }
        }

        // ---- epilogue: out = x(smem fp32) + res * tanh(acc) [+ bf16 copy] ----
        #pragma unroll
        for (int j = 0; j < 4; j++) {
            int col = wn * 32 + j * 8 + tg2;
            if (r0g < Nn) {
                float2 xv = *reinterpret_cast<const float2*>(&Ax[r0l * ASX + col]);
                float2 o;
                o.x = xv.x + resv * tanh_approx(acc[j][0]);
                o.y = xv.y + resv * tanh_approx(acc[j][1]);
                *reinterpret_cast<float2*>(out + (size_t)r0g * D + col) = o;
                if (outbf) {
                    __nv_bfloat162 ob = __floats2bfloat162_rn(o.x, o.y);
                    *reinterpret_cast<unsigned*>(outbf + (size_t)r0g * D + col) =
                        *reinterpret_cast<unsigned*>(&ob);
                }
            }
            if (r1g < Nn) {
                float2 xv = *reinterpret_cast<const float2*>(&Ax[r1l * ASX + col]);
                float2 o;
                o.x = xv.x + resv * tanh_approx(acc[j][2]);
                o.y = xv.y + resv * tanh_approx(acc[j][3]);
                *reinterpret_cast<float2*>(out + (size_t)r1g * D + col) = o;
                if (outbf) {
                    __nv_bfloat162 ob = __floats2bfloat162_rn(o.x, o.y);
                    *reinterpret_cast<unsigned*>(outbf + (size_t)r1g * D + col) =
                        *reinterpret_cast<unsigned*>(&ob);
                }
            }
        }
        __syncthreads();   // reads of buf complete before iter i+1 stages into it
        buf = (buf + 1) % NBUF;
    }
}

// ---------------------------------------------------------------------------
extern "C" void kernel_launch(void* const* d_in, const int* in_sizes, int n_in,
                              void* d_out, int out_size)
{
    const float* emb    = (const float*)d_in[0];
    const float* change = (const float*)d_in[1];
    const float* W1     = (const float*)d_in[2];
    const float* Wl1    = (const float*)d_in[3];
    const float* rel1   = (const float*)d_in[4];
    const float* W2     = (const float*)d_in[5];
    const float* Wl2    = (const float*)d_in[6];
    const float* rel2   = (const float*)d_in[7];
    const float* res    = (const float*)d_in[8];
    const float* jw     = (const float*)d_in[9];
    const float* ewj    = (const float*)d_in[10];
    const int*   ei     = (const int*)d_in[11];
    const int*   et     = (const int*)d_in[12];
    const int*   ej     = (const int*)d_in[13];

    int Nn = in_sizes[0] / D;
    int E  = in_sizes[12];
    int EJ = in_sizes[10];
    int ntiles = (Nn + BM - 1) / BM;
    int nscan = (Nn + SCAN_B - 1) / SCAN_B;
    size_t rowBytes = (size_t)Nn * D * sizeof(float);

    float* out_change = (float*)d_out;
    float* out_dch    = (float*)d_out + (size_t)Nn * D;

    void *p_agg, *p_hbf, *p_h, *p_cnt;
    cudaGetSymbolAddress(&p_agg, g_aggbf);
    cudaGetSymbolAddress(&p_hbf, g_hbf);
    cudaGetSymbolAddress(&p_h,   g_h);
    cudaGetSymbolAddress(&p_cnt, g_cnt);
    __nv_bfloat16* agg = (__nv_bfloat16*)p_agg;
    __nv_bfloat16* hbf = (__nv_bfloat16*)p_hbf;
    float* hbuf = (float*)p_h;

    cudaFuncSetAttribute(fused_gemm, cudaFuncAttributeMaxDynamicSharedMemorySize,
                         SMEM_BYTES);

    int convBlocks = (Nn + 7) / 8;

    // Strictly serial stream 0 — capture structure proven in R11/R13.
    // ---- CSR build (shared by both layers) ----
    cudaMemsetAsync(p_cnt, 0, (size_t)Nn * sizeof(int), 0);
    deg_count<<<(E + 255) / 256, 256>>>(ei, E);
    scan1<<<nscan, SCAN_B>>>(Nn);
    scan2<<<1, 256>>>(nscan);
    scan3<<<(Nn + 255) / 256, 256>>>(Nn);
    csr_fill<<<(E + 255) / 256, 256>>>(ei, et, E);

    // Layer 1: conv gathers fp32 emb; gemm emits fp32 h + bf16 h (near-free)
    conv_gather_f32<<<convBlocks, 256>>>(emb, rel1, agg, Nn);
    fused_gemm<<<152, 512, SMEM_BYTES>>>(emb, W1, Wl1, res, agg,
                                         hbuf, hbf, Nn, ntiles);

    // Layer 2: conv gathers bf16 h (halves conv2's LTS gather traffic)
    conv_gather_bf16<<<convBlocks, 256>>>(hbf, rel2, agg, Nn);
    fused_gemm<<<152, 512, SMEM_BYTES>>>(hbuf, W2, Wl2, res, agg,
                                         out_dch, (__nv_bfloat16*)nullptr,
                                         Nn, ntiles);

    // Jump diffusion accumulates directly onto dchange (fp32 emb)
    jump_scatter<<<2368, 256>>>(emb, ewj, jw, ej, out_dch, EJ);

    // change passthrough
    cudaMemcpyAsync(out_change, change, rowBytes, cudaMemcpyDeviceToDevice, 0);
}